// round 14
// baseline (speedup 1.0000x reference)
#include <cuda_runtime.h>
#include <cuda_bf16.h>
#include <cuda_fp16.h>
#include <cstdint>

#define D_MODEL  1024
#define N_HEADS  16
#define HEAD_DIM 64
#define SEQ_L    2048
#define BATCH    4
#define WINDOW   512

#define MTOT (BATCH * SEQ_L)          // 8192

__device__ __nv_bfloat16 g_qh[MTOT * D_MODEL];
__device__ __nv_bfloat16 g_ql[MTOT * D_MODEL];
__device__ __nv_bfloat16 g_kh[MTOT * D_MODEL];
__device__ __nv_bfloat16 g_kl[MTOT * D_MODEL];
__device__ __nv_bfloat16 g_vh[MTOT * D_MODEL];
__device__ __nv_bfloat16 g_vl[MTOT * D_MODEL];
__device__ __half        g_att[MTOT * D_MODEL];        // attention out (fp16)
__device__ __half        g_xh[MTOT * D_MODEL];         // fp16-rounded x
__device__ __half        g_wh[4 * D_MODEL * D_MODEL];  // fp16 Wq,Wk,Wv,Wo

__device__ __forceinline__ void mma_fp16(float* d, const uint32_t* a,
                                         uint32_t b0, uint32_t b1) {
    asm volatile(
        "mma.sync.aligned.m16n8k16.row.col.f32.f16.f16.f32 "
        "{%0,%1,%2,%3}, {%4,%5,%6,%7}, {%8,%9}, {%0,%1,%2,%3};"
        : "+f"(d[0]), "+f"(d[1]), "+f"(d[2]), "+f"(d[3])
        : "r"(a[0]), "r"(a[1]), "r"(a[2]), "r"(a[3]), "r"(b0), "r"(b1));
}
__device__ __forceinline__ void mma_bf16(float* d, const uint32_t* a,
                                         uint32_t b0, uint32_t b1) {
    asm volatile(
        "mma.sync.aligned.m16n8k16.row.col.f32.bf16.bf16.f32 "
        "{%0,%1,%2,%3}, {%4,%5,%6,%7}, {%8,%9}, {%0,%1,%2,%3};"
        : "+f"(d[0]), "+f"(d[1]), "+f"(d[2]), "+f"(d[3])
        : "r"(a[0]), "r"(a[1]), "r"(a[2]), "r"(a[3]), "r"(b0), "r"(b1));
}
__device__ __forceinline__ uint32_t smem_u32(const void* p) {
    uint32_t a;
    asm("{ .reg .u64 t; cvta.to.shared.u64 t, %1; cvt.u32.u64 %0, t; }"
        : "=r"(a) : "l"(p));
    return a;
}
__device__ __forceinline__ void ldsm_x4(uint32_t addr, uint32_t* r) {
    asm volatile(
        "ldmatrix.sync.aligned.m8n8.x4.shared.b16 {%0,%1,%2,%3}, [%4];"
        : "=r"(r[0]), "=r"(r[1]), "=r"(r[2]), "=r"(r[3]) : "r"(addr));
}
__device__ __forceinline__ void ldsm_x4_t(uint32_t addr, uint32_t* r) {
    asm volatile(
        "ldmatrix.sync.aligned.m8n8.x4.trans.shared.b16 {%0,%1,%2,%3}, [%4];"
        : "=r"(r[0]), "=r"(r[1]), "=r"(r[2]), "=r"(r[3]) : "r"(addr));
}
__device__ __forceinline__ void split_pair(float e0, float e1,
                                           uint32_t& h, uint32_t& l) {
    __nv_bfloat16 b0 = __float2bfloat16_rn(e0), b1 = __float2bfloat16_rn(e1);
    h = ((uint32_t)__bfloat16_as_ushort(b1) << 16) | __bfloat16_as_ushort(b0);
    float r0 = e0 - __bfloat162float(b0), r1 = e1 - __bfloat162float(b1);
    __nv_bfloat16 c0 = __float2bfloat16_rn(r0), c1 = __float2bfloat16_rn(r1);
    l = ((uint32_t)__bfloat16_as_ushort(c1) << 16) | __bfloat16_as_ushort(c0);
}

#define CP_ASYNC16(dst, src) \
    asm volatile("cp.async.cg.shared.global [%0], [%1], 16;" \
                 :: "r"(dst), "l"(src))
#define CP_COMMIT() asm volatile("cp.async.commit_group;")
#define CP_WAITG1() asm volatile("cp.async.wait_group 1;" ::: "memory")
#define CP_WAIT0()  asm volatile("cp.async.wait_group 0;" ::: "memory")

// ---------------------------------------------------------------------------
// Merged fp16 pre-round: y=0 -> x, y=1..4 -> Wq/Wk/Wv/Wo.
// ---------------------------------------------------------------------------
__global__ void round_fp16_multi(
    const float4* __restrict__ x,  __half* __restrict__ xh,
    const float4* __restrict__ wq, const float4* __restrict__ wk,
    const float4* __restrict__ wv, const float4* __restrict__ wo,
    __half* __restrict__ wh, int xn4, int wn4)
{
    const int y = blockIdx.y;
    const int i = blockIdx.x * blockDim.x + threadIdx.x;
    const float4* in;
    __half* out;
    int n4;
    if (y == 0)      { in = x;  out = xh;               n4 = xn4; }
    else if (y == 1) { in = wq; out = wh;               n4 = wn4; }
    else if (y == 2) { in = wk; out = wh + 4 * wn4;     n4 = wn4; }
    else if (y == 3) { in = wv; out = wh + 8 * wn4;     n4 = wn4; }
    else             { in = wo; out = wh + 12 * wn4;    n4 = wn4; }
    if (i < n4) {
        float4 v = in[i];
        __half2 h0 = __floats2half2_rn(v.x, v.y);
        __half2 h1 = __floats2half2_rn(v.z, v.w);
        *(uint2*)(out + 4 * i) =
            make_uint2(*(uint32_t*)&h0, *(uint32_t*)&h1);
    }
}

// ---------------------------------------------------------------------------
// fp16 GEMM, 3-stage cp.async, BK=64 (unchanged from round 13).
// ---------------------------------------------------------------------------
#define G2_STAGE 16384
#define G2_SMEM_BYTES (6 * G2_STAGE)     // 96 KB
#define NIT2 16                          // K / 64

template <bool SPLIT>
__global__ __launch_bounds__(256) void gemm_fp16_cp3(
    const __half* __restrict__ A, const __half* __restrict__ Wbase,
    size_t wstride,
    const float* __restrict__ b0, const float* __restrict__ b1,
    const float* __restrict__ b2,
    float* __restrict__ C0,
    __nv_bfloat16* __restrict__ H0, __nv_bfloat16* __restrict__ L0,
    __nv_bfloat16* __restrict__ H1, __nv_bfloat16* __restrict__ L1,
    __nv_bfloat16* __restrict__ H2, __nv_bfloat16* __restrict__ L2,
    int M, int N, int K)
{
    extern __shared__ char gsm[];
    const int z = blockIdx.z;
    const __half* W   = Wbase + (size_t)z * wstride;
    const float* bias = (z == 0) ? b0 : (z == 1) ? b1 : b2;

    const int tid    = threadIdx.x;
    const int warpId = tid >> 5;
    const int lane   = tid & 31;
    const int r      = lane >> 2;
    const int c      = lane & 3;
    const int warpM  = (warpId >> 2) * 64;
    const int warpN  = (warpId & 3) * 32;
    const int m0     = blockIdx.y * 128;
    const int n0     = blockIdx.x * 128;

    const int gRow = tid >> 1;
    const int hc   = tid & 1;
    const __half* Ag = A + (size_t)(m0 + gRow) * K + hc * 32;
    const __half* Wg = W + (size_t)(n0 + gRow) * K + hc * 32;

    uint32_t soff[4];
#pragma unroll
    for (int j = 0; j < 4; ++j)
        soff[j] = (uint32_t)gRow * 128 +
                  ((uint32_t)((hc * 4 + j) ^ (gRow & 7)) << 4);

    uint32_t asb[3], bsb[3];
#pragma unroll
    for (int s = 0; s < 3; ++s) {
        asb[s] = smem_u32(gsm + s * G2_STAGE);
        bsb[s] = smem_u32(gsm + (3 + s) * G2_STAGE);
    }

    const int lrow8 = lane & 7;
    const int tsel  = lane >> 3;
    const int aRow  = warpM + ((tsel & 1) << 3) + lrow8;
    const int aCa   = tsel >> 1;
    const int bRow  = warpN + ((tsel >> 1) << 3) + lrow8;
    const int bCa   = tsel & 1;

    float acc[4][4][4];
#pragma unroll
    for (int mt = 0; mt < 4; ++mt)
#pragma unroll
        for (int nt = 0; nt < 4; ++nt)
#pragma unroll
            for (int q = 0; q < 4; ++q) acc[mt][nt][q] = 0.f;

#pragma unroll
    for (int s = 0; s < 2; ++s) {
        const __half* An = Ag + s * 64;
        const __half* Wn = Wg + s * 64;
#pragma unroll
        for (int j = 0; j < 4; ++j) {
            CP_ASYNC16(asb[s] + soff[j], An + 8 * j);
            CP_ASYNC16(bsb[s] + soff[j], Wn + 8 * j);
        }
        CP_COMMIT();
    }

    int st = 0, sl = 2;
    for (int i = 0; i < NIT2; ++i) {
        CP_WAITG1();
        __syncthreads();

        if (i + 2 < NIT2) {
            const __half* An = Ag + (i + 2) * 64;
            const __half* Wn = Wg + (i + 2) * 64;
#pragma unroll
            for (int j = 0; j < 4; ++j) {
                CP_ASYNC16(asb[sl] + soff[j], An + 8 * j);
                CP_ASYNC16(bsb[sl] + soff[j], Wn + 8 * j);
            }
        }
        CP_COMMIT();

        const uint32_t a_s = asb[st], b_s = bsb[st];
#pragma unroll
        for (int ks = 0; ks < 4; ++ks) {
            uint32_t af[4][4];
            const uint32_t aChunk = (uint32_t)((2 * ks + aCa) ^ lrow8) << 4;
#pragma unroll
            for (int mt = 0; mt < 4; ++mt)
                ldsm_x4(a_s + ((uint32_t)(aRow + 16 * mt) << 7) + aChunk, af[mt]);

            uint32_t bf[2][4];
            const uint32_t bChunk = (uint32_t)((2 * ks + bCa) ^ lrow8) << 4;
#pragma unroll
            for (int p = 0; p < 2; ++p)
                ldsm_x4(b_s + ((uint32_t)(bRow + 16 * p) << 7) + bChunk, bf[p]);

#pragma unroll
            for (int nt = 0; nt < 4; ++nt) {
                const uint32_t bb0 = bf[nt >> 1][(nt & 1) << 1];
                const uint32_t bb1 = bf[nt >> 1][((nt & 1) << 1) + 1];
#pragma unroll
                for (int mt = 0; mt < 4; ++mt)
                    mma_fp16(acc[mt][nt], af[mt], bb0, bb1);
            }
        }
        st = (st == 2) ? 0 : st + 1;
        sl = (sl == 2) ? 0 : sl + 1;
    }

    if (SPLIT) {
        const float scl = (z == 0) ? 0.125f : 1.f;
        __nv_bfloat16* H = (z == 0) ? H0 : (z == 1) ? H1 : H2;
        __nv_bfloat16* L = (z == 0) ? L0 : (z == 1) ? L1 : L2;
#pragma unroll
        for (int nt = 0; nt < 4; ++nt) {
            const int col = n0 + warpN + 8 * nt + 2 * c;
            const float2 bv = *(const float2*)&bias[col];
#pragma unroll
            for (int mt = 0; mt < 4; ++mt) {
                const int row = m0 + warpM + 16 * mt + r;
                uint32_t hp, lp;
                split_pair((acc[mt][nt][0] + bv.x) * scl,
                           (acc[mt][nt][1] + bv.y) * scl, hp, lp);
                *(uint32_t*)&H[(size_t)row * N + col] = hp;
                *(uint32_t*)&L[(size_t)row * N + col] = lp;
                split_pair((acc[mt][nt][2] + bv.x) * scl,
                           (acc[mt][nt][3] + bv.y) * scl, hp, lp);
                *(uint32_t*)&H[(size_t)(row + 8) * N + col] = hp;
                *(uint32_t*)&L[(size_t)(row + 8) * N + col] = lp;
            }
        }
    } else {
#pragma unroll
        for (int nt = 0; nt < 4; ++nt) {
            const int col = n0 + warpN + 8 * nt + 2 * c;
            const float2 bv = *(const float2*)&bias[col];
#pragma unroll
            for (int mt = 0; mt < 4; ++mt) {
                const int row = m0 + warpM + 16 * mt + r;
                float2 o0 = make_float2(acc[mt][nt][0] + bv.x,
                                        acc[mt][nt][1] + bv.y);
                float2 o1 = make_float2(acc[mt][nt][2] + bv.x,
                                        acc[mt][nt][3] + bv.y);
                *(float2*)&C0[(size_t)row * N + col]       = o0;
                *(float2*)&C0[(size_t)(row + 8) * N + col] = o1;
            }
        }
    }
}

// ---------------------------------------------------------------------------
// Flash attention v3: 128-query CTA, warp tile 16q x 64keys.
// Softmax fully warp-private (quad shuffles); P stays in registers
// (accumulator layout == A-fragment layout for m16n8k16).
// One __syncthreads per key-tile. cp.async double-buffered K/V.
// smem: Qh(16K) Ql(16K) + 2 stages x (Kh Kl Vh Vl = 32K) = 96 KB.
// ---------------------------------------------------------------------------
#define AQ_H 0
#define AQ_L 16384
#define AKV0 32768
#define AKV_STRIDE 32768
#define ATTN_SMEM_BYTES (96 * 1024)

__global__ __launch_bounds__(256, 2) void attn_alibi_wp(
    const __nv_bfloat16* __restrict__ Qh_g, const __nv_bfloat16* __restrict__ Ql_g,
    const __nv_bfloat16* __restrict__ Kh_g, const __nv_bfloat16* __restrict__ Kl_g,
    const __nv_bfloat16* __restrict__ Vh_g, const __nv_bfloat16* __restrict__ Vl_g,
    const unsigned char* __restrict__ pad, __half* __restrict__ O)
{
    const int qt = blockIdx.x;            // 128-query tile
    const int bh = blockIdx.y;
    const int b  = bh >> 4;
    const int h  = bh & 15;

    extern __shared__ char smc[];
    const uint32_t smb = smem_u32(smc);

    __shared__ float pads[2][64];

    const int tid  = threadIdx.x;
    const int warp = tid >> 5;
    const int lane = tid & 31;
    const int r    = lane >> 2;
    const int c    = lane & 3;

    const int lrow8 = lane & 7;
    const int tsel  = lane >> 3;

    // Q A-frag: rows [16*warp, +16)
    const int aRow = 16 * warp + ((tsel & 1) << 3) + lrow8;
    const int aCa  = tsel >> 1;
    const uint32_t qh_b = smb + AQ_H + (uint32_t)aRow * 128;
    const uint32_t ql_b = smb + AQ_L + (uint32_t)aRow * 128;

    // K B-frag: rows 16p + ((tsel>>1)<<3) + lrow8; chunk 2ks + (tsel&1)
    const uint32_t kRowOff = (uint32_t)(((tsel >> 1) << 3) + lrow8) * 128;
    const int kCa = tsel & 1;
    // V trans: k-rows 16ks + ((tsel&1)<<3)+lrow8; d-chunks 2p + (tsel>>1)
    const uint32_t vRowOff = (uint32_t)(((tsel & 1) << 3) + lrow8) * 128;
    const int vCa = tsel >> 1;

    const float slope = exp2f(-0.5f * (float)(h + 1));
    const unsigned char* padb = pad + (size_t)b * SEQ_L;

    // K/V loader: row = tid>>2 (0..63), chunks (tid&3)*2, +1
    const int ldRow = tid >> 2;
    const uint32_t off0 = (uint32_t)ldRow * 128 +
                          ((uint32_t)(((tid & 3) * 2) ^ (ldRow & 7)) << 4);
    const uint32_t off1 = (uint32_t)ldRow * 128 +
                          ((uint32_t)(((tid & 3) * 2 + 1) ^ (ldRow & 7)) << 4);
    const size_t gcol = (size_t)h * HEAD_DIM + (tid & 3) * 16;

    const int kt_lo = (qt >= 4) ? (2 * qt - 8) : 0;
    const int kt_hi = 2 * qt + 1;

    // ---- prologue: Q tile (128 rows) + first K/V tile + pads ----
    {
        const int qRow = tid >> 1;
        const size_t qidx =
            ((size_t)(b * SEQ_L + qt * 128 + qRow)) * D_MODEL +
            (size_t)h * HEAD_DIM + (tid & 1) * 32;
#pragma unroll
        for (int j = 0; j < 4; ++j) {
            const int jj = (tid & 1) * 4 + j;
            const uint32_t qo = (uint32_t)qRow * 128 +
                                ((uint32_t)(jj ^ (qRow & 7)) << 4);
            CP_ASYNC16(smb + AQ_H + qo, Qh_g + qidx + 8 * j);
            CP_ASYNC16(smb + AQ_L + qo, Ql_g + qidx + 8 * j);
        }
        const size_t kidx = ((size_t)(b * SEQ_L + kt_lo * 64 + ldRow)) * D_MODEL + gcol;
        const uint32_t s0 = smb + AKV0;
        CP_ASYNC16(s0 + off0,          Kh_g + kidx);
        CP_ASYNC16(s0 + off1,          Kh_g + kidx + 8);
        CP_ASYNC16(s0 + 8192 + off0,   Kl_g + kidx);
        CP_ASYNC16(s0 + 8192 + off1,   Kl_g + kidx + 8);
        CP_ASYNC16(s0 + 16384 + off0,  Vh_g + kidx);
        CP_ASYNC16(s0 + 16384 + off1,  Vh_g + kidx + 8);
        CP_ASYNC16(s0 + 24576 + off0,  Vl_g + kidx);
        CP_ASYNC16(s0 + 24576 + off1,  Vl_g + kidx + 8);
        CP_COMMIT();
    }
    if (tid < 64)
        pads[kt_lo & 1][tid] = padb[kt_lo * 64 + tid] ? -1e30f : 0.f;

    float Oacc[8][4];
#pragma unroll
    for (int nt = 0; nt < 8; ++nt)
#pragma unroll
        for (int q = 0; q < 4; ++q) Oacc[nt][q] = 0.f;

    const int row0 = 16 * warp + r;
    // m init -1e29: fully-masked first tiles give exp(-1e30 + 1e29) -> 0
    float m0r = -1e29f, m1r = -1e29f, l0r = 0.f, l1r = 0.f;

    int st = 0;
    for (int kt = kt_lo; kt <= kt_hi; ++kt) {
        CP_WAIT0();
        __syncthreads();   // stage st ready; prior-iteration reads complete

        if (kt < kt_hi) {
            const size_t kidx =
                ((size_t)(b * SEQ_L + (kt + 1) * 64 + ldRow)) * D_MODEL + gcol;
            const uint32_t s1 = smb + AKV0 + (uint32_t)(st ^ 1) * AKV_STRIDE;
            CP_ASYNC16(s1 + off0,          Kh_g + kidx);
            CP_ASYNC16(s1 + off1,          Kh_g + kidx + 8);
            CP_ASYNC16(s1 + 8192 + off0,   Kl_g + kidx);
            CP_ASYNC16(s1 + 8192 + off1,   Kl_g + kidx + 8);
            CP_ASYNC16(s1 + 16384 + off0,  Vh_g + kidx);
            CP_ASYNC16(s1 + 16384 + off1,  Vh_g + kidx + 8);
            CP_ASYNC16(s1 + 24576 + off0,  Vl_g + kidx);
            CP_ASYNC16(s1 + 24576 + off1,  Vl_g + kidx + 8);
            CP_COMMIT();
            if (tid < 64)
                pads[(kt + 1) & 1][tid] = padb[(kt + 1) * 64 + tid] ? -1e30f : 0.f;
        }

        const uint32_t stb  = smb + AKV0 + (uint32_t)st * AKV_STRIDE;
        const uint32_t kh_b = stb + kRowOff;
        const uint32_t vh_b = stb + 16384u + vRowOff;
        const float* padc = pads[kt & 1];

        // ---- S = Q.K^T (8 n-tiles of 8 keys) ----
        float Sacc[8][4];
#pragma unroll
        for (int nt = 0; nt < 8; ++nt)
#pragma unroll
            for (int q = 0; q < 4; ++q) Sacc[nt][q] = 0.f;

#pragma unroll
        for (int ks = 0; ks < 4; ++ks) {
            uint32_t ah[4], al[4];
            const uint32_t axo = ((uint32_t)((2 * ks + aCa) ^ lrow8) << 4);
            ldsm_x4(qh_b + axo, ah);
            ldsm_x4(ql_b + axo, al);
            const uint32_t kxo = ((uint32_t)((2 * ks + kCa) ^ lrow8) << 4);
#pragma unroll
            for (int p = 0; p < 4; ++p) {
                uint32_t bh[4], bl[4];
                ldsm_x4(kh_b + (uint32_t)p * 2048 + kxo, bh);
                ldsm_x4(kh_b + 8192 + (uint32_t)p * 2048 + kxo, bl);
#pragma unroll
                for (int q2 = 0; q2 < 2; ++q2) {
                    float* dst = Sacc[2 * p + q2];
                    const uint32_t bh0 = bh[2 * q2], bh1 = bh[2 * q2 + 1];
                    const uint32_t bl0 = bl[2 * q2], bl1 = bl[2 * q2 + 1];
                    mma_bf16(dst, ah, bh0, bh1);
                    mma_bf16(dst, ah, bl0, bl1);
                    mma_bf16(dst, al, bh0, bh1);
                }
            }
        }

        // ---- mask + ALiBi + warp-private row max ----
        const int gi0 = qt * 128 + row0;
        const int gi1 = gi0 + 8;
        float mx0 = -1e30f, mx1 = -1e30f;
#pragma unroll
        for (int nt = 0; nt < 8; ++nt) {
            const int jl = 8 * nt + 2 * c;
            const int gj0 = kt * 64 + jl, gj1 = gj0 + 1;
            const float pd0 = padc[jl], pd1 = padc[jl + 1];
            float s;
            s = Sacc[nt][0] + slope * (float)(gj0 - gi0) + pd0;
            if (gj0 > gi0 || gj0 < gi0 - WINDOW) s = -1e30f;
            Sacc[nt][0] = s; mx0 = fmaxf(mx0, s);
            s = Sacc[nt][1] + slope * (float)(gj1 - gi0) + pd1;
            if (gj1 > gi0 || gj1 < gi0 - WINDOW) s = -1e30f;
            Sacc[nt][1] = s; mx0 = fmaxf(mx0, s);
            s = Sacc[nt][2] + slope * (float)(gj0 - gi1) + pd0;
            if (gj0 > gi1 || gj0 < gi1 - WINDOW) s = -1e30f;
            Sacc[nt][2] = s; mx1 = fmaxf(mx1, s);
            s = Sacc[nt][3] + slope * (float)(gj1 - gi1) + pd1;
            if (gj1 > gi1 || gj1 < gi1 - WINDOW) s = -1e30f;
            Sacc[nt][3] = s; mx1 = fmaxf(mx1, s);
        }
        mx0 = fmaxf(mx0, __shfl_xor_sync(0xffffffffu, mx0, 1));
        mx0 = fmaxf(mx0, __shfl_xor_sync(0xffffffffu, mx0, 2));
        mx1 = fmaxf(mx1, __shfl_xor_sync(0xffffffffu, mx1, 1));
        mx1 = fmaxf(mx1, __shfl_xor_sync(0xffffffffu, mx1, 2));

        const float mn0 = fmaxf(m0r, mx0);
        const float mn1 = fmaxf(m1r, mx1);
        const float sc0 = __expf(m0r - mn0);
        const float sc1 = __expf(m1r - mn1);
        m0r = mn0; m1r = mn1;

        // ---- P = exp(S - m) into Sacc; row sums; rescale O ----
        float rs0 = 0.f, rs1 = 0.f;
#pragma unroll
        for (int nt = 0; nt < 8; ++nt) {
            float p0 = __expf(Sacc[nt][0] - mn0);
            float p1 = __expf(Sacc[nt][1] - mn0);
            float p2 = __expf(Sacc[nt][2] - mn1);
            float p3 = __expf(Sacc[nt][3] - mn1);
            Sacc[nt][0] = p0; Sacc[nt][1] = p1;
            Sacc[nt][2] = p2; Sacc[nt][3] = p3;
            rs0 += p0 + p1; rs1 += p2 + p3;
            Oacc[nt][0] *= sc0; Oacc[nt][1] *= sc0;
            Oacc[nt][2] *= sc1; Oacc[nt][3] *= sc1;
        }
        rs0 += __shfl_xor_sync(0xffffffffu, rs0, 1);
        rs0 += __shfl_xor_sync(0xffffffffu, rs0, 2);
        rs1 += __shfl_xor_sync(0xffffffffu, rs1, 1);
        rs1 += __shfl_xor_sync(0xffffffffu, rs1, 2);
        l0r = l0r * sc0 + rs0;
        l1r = l1r * sc1 + rs1;

        // ---- O += P.V : P fragments straight from registers ----
#pragma unroll
        for (int ks = 0; ks < 4; ++ks) {
            uint32_t ah[4], al[4];
            split_pair(Sacc[2 * ks][0],     Sacc[2 * ks][1],     ah[0], al[0]);
            split_pair(Sacc[2 * ks][2],     Sacc[2 * ks][3],     ah[1], al[1]);
            split_pair(Sacc[2 * ks + 1][0], Sacc[2 * ks + 1][1], ah[2], al[2]);
            split_pair(Sacc[2 * ks + 1][2], Sacc[2 * ks + 1][3], ah[3], al[3]);
#pragma unroll
            for (int p = 0; p < 4; ++p) {
                uint32_t bvh[4], bvl[4];
                const uint32_t vxo = (uint32_t)ks * 2048 +
                    (((uint32_t)(2 * p + vCa) ^ lrow8) << 4);
                ldsm_x4_t(vh_b + vxo, bvh);
                ldsm_x4_t(vh_b + 8192 + vxo, bvl);
#pragma unroll
                for (int q2 = 0; q2 < 2; ++q2) {
                    float* dst = Oacc[2 * p + q2];
                    const uint32_t bh0 = bvh[2 * q2], bh1 = bvh[2 * q2 + 1];
                    const uint32_t bl0 = bvl[2 * q2], bl1 = bvl[2 * q2 + 1];
                    mma_bf16(dst, ah, bh0, bh1);
                    mma_bf16(dst, ah, bl0, bl1);
                    mma_bf16(dst, al, bh0, bh1);
                }
            }
        }
        st ^= 1;
    }

    const float inv0 = 1.f / l0r;
    const float inv1 = 1.f / l1r;
    const int gi0 = qt * 128 + row0;
    __half* Ob = O + ((size_t)b * SEQ_L + gi0) * D_MODEL + h * HEAD_DIM;
#pragma unroll
    for (int nt = 0; nt < 8; ++nt) {
        const int dcol = 8 * nt + 2 * c;
        __half2 o0 = __floats2half2_rn(Oacc[nt][0] * inv0, Oacc[nt][1] * inv0);
        __half2 o1 = __floats2half2_rn(Oacc[nt][2] * inv1, Oacc[nt][3] * inv1);
        *(__half2*)(Ob + dcol)               = o0;
        *(__half2*)(Ob + 8 * D_MODEL + dcol) = o1;
    }
}

// ---------------------------------------------------------------------------
extern "C" void kernel_launch(void* const* d_in, const int* in_sizes, int n_in,
                              void* d_out, int out_size)
{
    const float* x  = (const float*)d_in[0];
    const unsigned char* pad = (const unsigned char*)d_in[1];
    const float* Wq = (const float*)d_in[2];
    const float* bq = (const float*)d_in[3];
    const float* Wk = (const float*)d_in[4];
    const float* bk = (const float*)d_in[5];
    const float* Wv = (const float*)d_in[6];
    const float* bv = (const float*)d_in[7];
    const float* Wo = (const float*)d_in[8];
    const float* bo = (const float*)d_in[9];
    float* out = (float*)d_out;

    __nv_bfloat16 *qh, *ql, *kh, *kl, *vh, *vl;
    __half *att, *xh, *wh;
    cudaGetSymbolAddress((void**)&qh,  g_qh);
    cudaGetSymbolAddress((void**)&ql,  g_ql);
    cudaGetSymbolAddress((void**)&kh,  g_kh);
    cudaGetSymbolAddress((void**)&kl,  g_kl);
    cudaGetSymbolAddress((void**)&vh,  g_vh);
    cudaGetSymbolAddress((void**)&vl,  g_vl);
    cudaGetSymbolAddress((void**)&att, g_att);
    cudaGetSymbolAddress((void**)&xh,  g_xh);
    cudaGetSymbolAddress((void**)&wh,  g_wh);

    cudaFuncSetAttribute(gemm_fp16_cp3<true>,
                         cudaFuncAttributeMaxDynamicSharedMemorySize,
                         G2_SMEM_BYTES);
    cudaFuncSetAttribute(gemm_fp16_cp3<false>,
                         cudaFuncAttributeMaxDynamicSharedMemorySize,
                         G2_SMEM_BYTES);
    cudaFuncSetAttribute(attn_alibi_wp,
                         cudaFuncAttributeMaxDynamicSharedMemorySize,
                         ATTN_SMEM_BYTES);

    const int WN  = D_MODEL * D_MODEL;
    const int xn4 = MTOT * D_MODEL / 4;
    const int wn4 = WN / 4;
    dim3 rgrid((xn4 + 255) / 256, 5);
    round_fp16_multi<<<rgrid, 256>>>((const float4*)x, xh,
                                     (const float4*)Wq, (const float4*)Wk,
                                     (const float4*)Wv, (const float4*)Wo,
                                     wh, xn4, wn4);

    dim3 qkv_grid(D_MODEL / 128, MTOT / 128, 3);
    gemm_fp16_cp3<true><<<qkv_grid, 256, G2_SMEM_BYTES>>>(
        xh, wh, (size_t)WN, bq, bk, bv, nullptr,
        qh, ql, kh, kl, vh, vl, MTOT, D_MODEL, D_MODEL);

    dim3 agrid(SEQ_L / 128, BATCH * N_HEADS);   // (16, 64)
    attn_alibi_wp<<<agrid, 256, ATTN_SMEM_BYTES>>>(
        qh, ql, kh, kl, vh, vl, pad, att);

    dim3 o_grid(D_MODEL / 128, MTOT / 128, 1);
    gemm_fp16_cp3<false><<<o_grid, 256, G2_SMEM_BYTES>>>(
        att, wh + 3 * (size_t)WN, (size_t)0, bo, bo, bo, out,
        nullptr, nullptr, nullptr, nullptr, nullptr, nullptr,
        MTOT, D_MODEL, D_MODEL);
}

// round 15
// speedup vs baseline: 1.6731x; 1.6731x over previous
#include <cuda_runtime.h>
#include <cuda_bf16.h>
#include <cuda_fp16.h>
#include <cstdint>

#define D_MODEL  1024
#define N_HEADS  16
#define HEAD_DIM 64
#define SEQ_L    2048
#define BATCH    4
#define WINDOW   512

#define MTOT (BATCH * SEQ_L)          // 8192

__device__ __nv_bfloat16 g_qh[MTOT * D_MODEL];
__device__ __nv_bfloat16 g_ql[MTOT * D_MODEL];
__device__ __nv_bfloat16 g_kh[MTOT * D_MODEL];
__device__ __nv_bfloat16 g_kl[MTOT * D_MODEL];
__device__ __half        g_vf[MTOT * D_MODEL];         // V as fp16 plane
__device__ __half        g_att[MTOT * D_MODEL];        // attention out (fp16)
__device__ __half        g_xh[MTOT * D_MODEL];         // fp16-rounded x
__device__ __half        g_wh[4 * D_MODEL * D_MODEL];  // fp16 Wq,Wk,Wv,Wo

__device__ __forceinline__ void mma_fp16(float* d, const uint32_t* a,
                                         uint32_t b0, uint32_t b1) {
    asm volatile(
        "mma.sync.aligned.m16n8k16.row.col.f32.f16.f16.f32 "
        "{%0,%1,%2,%3}, {%4,%5,%6,%7}, {%8,%9}, {%0,%1,%2,%3};"
        : "+f"(d[0]), "+f"(d[1]), "+f"(d[2]), "+f"(d[3])
        : "r"(a[0]), "r"(a[1]), "r"(a[2]), "r"(a[3]), "r"(b0), "r"(b1));
}
__device__ __forceinline__ void mma_bf16(float* d, const uint32_t* a,
                                         uint32_t b0, uint32_t b1) {
    asm volatile(
        "mma.sync.aligned.m16n8k16.row.col.f32.bf16.bf16.f32 "
        "{%0,%1,%2,%3}, {%4,%5,%6,%7}, {%8,%9}, {%0,%1,%2,%3};"
        : "+f"(d[0]), "+f"(d[1]), "+f"(d[2]), "+f"(d[3])
        : "r"(a[0]), "r"(a[1]), "r"(a[2]), "r"(a[3]), "r"(b0), "r"(b1));
}
__device__ __forceinline__ uint32_t smem_u32(const void* p) {
    uint32_t a;
    asm("{ .reg .u64 t; cvta.to.shared.u64 t, %1; cvt.u32.u64 %0, t; }"
        : "=r"(a) : "l"(p));
    return a;
}
__device__ __forceinline__ void ldsm_x4(uint32_t addr, uint32_t* r) {
    asm volatile(
        "ldmatrix.sync.aligned.m8n8.x4.shared.b16 {%0,%1,%2,%3}, [%4];"
        : "=r"(r[0]), "=r"(r[1]), "=r"(r[2]), "=r"(r[3]) : "r"(addr));
}
__device__ __forceinline__ void ldsm_x4_t(uint32_t addr, uint32_t* r) {
    asm volatile(
        "ldmatrix.sync.aligned.m8n8.x4.trans.shared.b16 {%0,%1,%2,%3}, [%4];"
        : "=r"(r[0]), "=r"(r[1]), "=r"(r[2]), "=r"(r[3]) : "r"(addr));
}
__device__ __forceinline__ void split_pair(float e0, float e1,
                                           uint32_t& h, uint32_t& l) {
    __nv_bfloat16 b0 = __float2bfloat16_rn(e0), b1 = __float2bfloat16_rn(e1);
    h = ((uint32_t)__bfloat16_as_ushort(b1) << 16) | __bfloat16_as_ushort(b0);
    float r0 = e0 - __bfloat162float(b0), r1 = e1 - __bfloat162float(b1);
    __nv_bfloat16 c0 = __float2bfloat16_rn(r0), c1 = __float2bfloat16_rn(r1);
    l = ((uint32_t)__bfloat16_as_ushort(c1) << 16) | __bfloat16_as_ushort(c0);
}

#define CP_ASYNC16(dst, src) \
    asm volatile("cp.async.cg.shared.global [%0], [%1], 16;" \
                 :: "r"(dst), "l"(src))
#define CP_COMMIT() asm volatile("cp.async.commit_group;")
#define CP_WAITG1() asm volatile("cp.async.wait_group 1;" ::: "memory")
#define CP_WAIT0()  asm volatile("cp.async.wait_group 0;" ::: "memory")

// ---------------------------------------------------------------------------
// Merged fp16 pre-round: y=0 -> x, y=1..4 -> Wq/Wk/Wv/Wo.
// ---------------------------------------------------------------------------
__global__ void round_fp16_multi(
    const float4* __restrict__ x,  __half* __restrict__ xh,
    const float4* __restrict__ wq, const float4* __restrict__ wk,
    const float4* __restrict__ wv, const float4* __restrict__ wo,
    __half* __restrict__ wh, int xn4, int wn4)
{
    const int y = blockIdx.y;
    const int i = blockIdx.x * blockDim.x + threadIdx.x;
    const float4* in;
    __half* out;
    int n4;
    if (y == 0)      { in = x;  out = xh;               n4 = xn4; }
    else if (y == 1) { in = wq; out = wh;               n4 = wn4; }
    else if (y == 2) { in = wk; out = wh + 4 * wn4;     n4 = wn4; }
    else if (y == 3) { in = wv; out = wh + 8 * wn4;     n4 = wn4; }
    else             { in = wo; out = wh + 12 * wn4;    n4 = wn4; }
    if (i < n4) {
        float4 v = in[i];
        __half2 h0 = __floats2half2_rn(v.x, v.y);
        __half2 h1 = __floats2half2_rn(v.z, v.w);
        *(uint2*)(out + 4 * i) =
            make_uint2(*(uint32_t*)&h0, *(uint32_t*)&h1);
    }
}

// ---------------------------------------------------------------------------
// fp16 GEMM, 3-stage cp.async, BK=64.
// SPLIT: z==0 -> Q bf16 hi/lo (x0.125); z==1 -> K bf16 hi/lo; z==2 -> V fp16.
// ---------------------------------------------------------------------------
#define G2_STAGE 16384
#define G2_SMEM_BYTES (6 * G2_STAGE)     // 96 KB
#define NIT2 16                          // K / 64

template <bool SPLIT>
__global__ __launch_bounds__(256) void gemm_fp16_cp3(
    const __half* __restrict__ A, const __half* __restrict__ Wbase,
    size_t wstride,
    const float* __restrict__ b0, const float* __restrict__ b1,
    const float* __restrict__ b2,
    float* __restrict__ C0,
    __nv_bfloat16* __restrict__ H0, __nv_bfloat16* __restrict__ L0,
    __nv_bfloat16* __restrict__ H1, __nv_bfloat16* __restrict__ L1,
    __half* __restrict__ VF,
    int M, int N, int K)
{
    extern __shared__ char gsm[];
    const int z = blockIdx.z;
    const __half* W   = Wbase + (size_t)z * wstride;
    const float* bias = (z == 0) ? b0 : (z == 1) ? b1 : b2;

    const int tid    = threadIdx.x;
    const int warpId = tid >> 5;
    const int lane   = tid & 31;
    const int r      = lane >> 2;
    const int c      = lane & 3;
    const int warpM  = (warpId >> 2) * 64;
    const int warpN  = (warpId & 3) * 32;
    const int m0     = blockIdx.y * 128;
    const int n0     = blockIdx.x * 128;

    const int gRow = tid >> 1;
    const int hc   = tid & 1;
    const __half* Ag = A + (size_t)(m0 + gRow) * K + hc * 32;
    const __half* Wg = W + (size_t)(n0 + gRow) * K + hc * 32;

    uint32_t soff[4];
#pragma unroll
    for (int j = 0; j < 4; ++j)
        soff[j] = (uint32_t)gRow * 128 +
                  ((uint32_t)((hc * 4 + j) ^ (gRow & 7)) << 4);

    uint32_t asb[3], bsb[3];
#pragma unroll
    for (int s = 0; s < 3; ++s) {
        asb[s] = smem_u32(gsm + s * G2_STAGE);
        bsb[s] = smem_u32(gsm + (3 + s) * G2_STAGE);
    }

    const int lrow8 = lane & 7;
    const int tsel  = lane >> 3;
    const int aRow  = warpM + ((tsel & 1) << 3) + lrow8;
    const int aCa   = tsel >> 1;
    const int bRow  = warpN + ((tsel >> 1) << 3) + lrow8;
    const int bCa   = tsel & 1;

    float acc[4][4][4];
#pragma unroll
    for (int mt = 0; mt < 4; ++mt)
#pragma unroll
        for (int nt = 0; nt < 4; ++nt)
#pragma unroll
            for (int q = 0; q < 4; ++q) acc[mt][nt][q] = 0.f;

#pragma unroll
    for (int s = 0; s < 2; ++s) {
        const __half* An = Ag + s * 64;
        const __half* Wn = Wg + s * 64;
#pragma unroll
        for (int j = 0; j < 4; ++j) {
            CP_ASYNC16(asb[s] + soff[j], An + 8 * j);
            CP_ASYNC16(bsb[s] + soff[j], Wn + 8 * j);
        }
        CP_COMMIT();
    }

    int st = 0, sl = 2;
    for (int i = 0; i < NIT2; ++i) {
        CP_WAITG1();
        __syncthreads();

        if (i + 2 < NIT2) {
            const __half* An = Ag + (i + 2) * 64;
            const __half* Wn = Wg + (i + 2) * 64;
#pragma unroll
            for (int j = 0; j < 4; ++j) {
                CP_ASYNC16(asb[sl] + soff[j], An + 8 * j);
                CP_ASYNC16(bsb[sl] + soff[j], Wn + 8 * j);
            }
        }
        CP_COMMIT();

        const uint32_t a_s = asb[st], b_s = bsb[st];
#pragma unroll
        for (int ks = 0; ks < 4; ++ks) {
            uint32_t af[4][4];
            const uint32_t aChunk = (uint32_t)((2 * ks + aCa) ^ lrow8) << 4;
#pragma unroll
            for (int mt = 0; mt < 4; ++mt)
                ldsm_x4(a_s + ((uint32_t)(aRow + 16 * mt) << 7) + aChunk, af[mt]);

            uint32_t bf[2][4];
            const uint32_t bChunk = (uint32_t)((2 * ks + bCa) ^ lrow8) << 4;
#pragma unroll
            for (int p = 0; p < 2; ++p)
                ldsm_x4(b_s + ((uint32_t)(bRow + 16 * p) << 7) + bChunk, bf[p]);

#pragma unroll
            for (int nt = 0; nt < 4; ++nt) {
                const uint32_t bb0 = bf[nt >> 1][(nt & 1) << 1];
                const uint32_t bb1 = bf[nt >> 1][((nt & 1) << 1) + 1];
#pragma unroll
                for (int mt = 0; mt < 4; ++mt)
                    mma_fp16(acc[mt][nt], af[mt], bb0, bb1);
            }
        }
        st = (st == 2) ? 0 : st + 1;
        sl = (sl == 2) ? 0 : sl + 1;
    }

    if (SPLIT) {
        if (z == 2) {
            // V: fp16 single plane
#pragma unroll
            for (int nt = 0; nt < 4; ++nt) {
                const int col = n0 + warpN + 8 * nt + 2 * c;
                const float2 bv = *(const float2*)&bias[col];
#pragma unroll
                for (int mt = 0; mt < 4; ++mt) {
                    const int row = m0 + warpM + 16 * mt + r;
                    __half2 v0 = __floats2half2_rn(acc[mt][nt][0] + bv.x,
                                                   acc[mt][nt][1] + bv.y);
                    __half2 v1 = __floats2half2_rn(acc[mt][nt][2] + bv.x,
                                                   acc[mt][nt][3] + bv.y);
                    *(__half2*)&VF[(size_t)row * N + col]       = v0;
                    *(__half2*)&VF[(size_t)(row + 8) * N + col] = v1;
                }
            }
        } else {
            const float scl = (z == 0) ? 0.125f : 1.f;
            __nv_bfloat16* H = (z == 0) ? H0 : H1;
            __nv_bfloat16* L = (z == 0) ? L0 : L1;
#pragma unroll
            for (int nt = 0; nt < 4; ++nt) {
                const int col = n0 + warpN + 8 * nt + 2 * c;
                const float2 bv = *(const float2*)&bias[col];
#pragma unroll
                for (int mt = 0; mt < 4; ++mt) {
                    const int row = m0 + warpM + 16 * mt + r;
                    uint32_t hp, lp;
                    split_pair((acc[mt][nt][0] + bv.x) * scl,
                               (acc[mt][nt][1] + bv.y) * scl, hp, lp);
                    *(uint32_t*)&H[(size_t)row * N + col] = hp;
                    *(uint32_t*)&L[(size_t)row * N + col] = lp;
                    split_pair((acc[mt][nt][2] + bv.x) * scl,
                               (acc[mt][nt][3] + bv.y) * scl, hp, lp);
                    *(uint32_t*)&H[(size_t)(row + 8) * N + col] = hp;
                    *(uint32_t*)&L[(size_t)(row + 8) * N + col] = lp;
                }
            }
        }
    } else {
#pragma unroll
        for (int nt = 0; nt < 4; ++nt) {
            const int col = n0 + warpN + 8 * nt + 2 * c;
            const float2 bv = *(const float2*)&bias[col];
#pragma unroll
            for (int mt = 0; mt < 4; ++mt) {
                const int row = m0 + warpM + 16 * mt + r;
                float2 o0 = make_float2(acc[mt][nt][0] + bv.x,
                                        acc[mt][nt][1] + bv.y);
                float2 o1 = make_float2(acc[mt][nt][2] + bv.x,
                                        acc[mt][nt][3] + bv.y);
                *(float2*)&C0[(size_t)row * N + col]       = o0;
                *(float2*)&C0[(size_t)(row + 8) * N + col] = o1;
            }
        }
    }
}

// ---------------------------------------------------------------------------
// Flash attention (round-13 structure): 64q CTA, warp tile 16q x 32keys.
// S: bf16x2 3-term. PV: fp16 single plane (P fp16, V fp16).
// Registerized m/l, 3 barriers/tile, cp.async double-buffered K/V.
// smem: Qh(8K) Ql(8K) Pf(8K) + 2 stages x (Kh Kl Vf = 24K) = 72 KB.
// ---------------------------------------------------------------------------
#define AQ_H 0
#define AQ_L 8192
#define AP_F 16384
#define AKV0 24576
#define AKV_STRIDE 24576
#define ATTN_SMEM_BYTES (AKV0 + 2 * AKV_STRIDE)   // 72 KB

__global__ __launch_bounds__(256, 2) void attn_alibi_cp(
    const __nv_bfloat16* __restrict__ Qh_g, const __nv_bfloat16* __restrict__ Ql_g,
    const __nv_bfloat16* __restrict__ Kh_g, const __nv_bfloat16* __restrict__ Kl_g,
    const __half* __restrict__ Vf_g,
    const unsigned char* __restrict__ pad, __half* __restrict__ O)
{
    const int qt = blockIdx.x;
    const int bh = blockIdx.y;
    const int b  = bh >> 4;
    const int h  = bh & 15;

    extern __shared__ char smc[];
    const uint32_t smb = smem_u32(smc);

    __shared__ float redA[64][2];
    __shared__ float redB[64][2];
    __shared__ float pads[2][64];

    const int tid  = threadIdx.x;
    const int warp = tid >> 5;
    const int lane = tid & 31;
    const int r    = lane >> 2;
    const int c    = lane & 3;
    const int wq   = warp >> 1;
    const int wk   = warp & 1;

    const int lrow8 = lane & 7;
    const int tsel  = lane >> 3;

    // A-frag geometry (Q and P)
    const int aRow = 16 * wq + ((tsel & 1) << 3) + lrow8;
    const int aCa  = tsel >> 1;
    const int aR7  = aRow & 7;
    const uint32_t qh_b = smb + AQ_H + (uint32_t)aRow * 128;
    const uint32_t ql_b = smb + AQ_L + (uint32_t)aRow * 128;
    const uint32_t pf_b = smb + AP_F + (uint32_t)aRow * 128;

    // K B-frag geometry
    const int kRow = 32 * wk + ((tsel >> 1) << 3) + lrow8;
    const int kCa  = tsel & 1;
    const int kR7  = kRow & 7;
    const uint32_t khRel = (uint32_t)kRow * 128;
    // V trans B-frag geometry
    const int vRow = ((tsel & 1) << 3) + lrow8;
    const int vCa  = 4 * wk + (tsel >> 1);
    const int vR7  = vRow & 7;
    const uint32_t vfRel = 16384u + (uint32_t)vRow * 128;

    const float slope = exp2f(-0.5f * (float)(h + 1));
    const unsigned char* padb = pad + (size_t)b * SEQ_L;

    const int ldRow = tid >> 2;
    const uint32_t off0 = (uint32_t)ldRow * 128 +
                          ((uint32_t)(((tid & 3) * 2) ^ (ldRow & 7)) << 4);
    const uint32_t off1 = (uint32_t)ldRow * 128 +
                          ((uint32_t)(((tid & 3) * 2 + 1) ^ (ldRow & 7)) << 4);
    const size_t gcol = (size_t)h * HEAD_DIM + (tid & 3) * 16;

    const int kt_lo = (qt >= 8) ? (qt - 8) : 0;

    // ---- prologue: Q tile + first K/V tile + pads ----
    {
        const size_t qidx = ((size_t)(b * SEQ_L + qt * 64 + ldRow)) * D_MODEL + gcol;
        CP_ASYNC16(smb + AQ_H + off0, Qh_g + qidx);
        CP_ASYNC16(smb + AQ_H + off1, Qh_g + qidx + 8);
        CP_ASYNC16(smb + AQ_L + off0, Ql_g + qidx);
        CP_ASYNC16(smb + AQ_L + off1, Ql_g + qidx + 8);
        const size_t kidx = ((size_t)(b * SEQ_L + kt_lo * 64 + ldRow)) * D_MODEL + gcol;
        const uint32_t s0 = smb + AKV0;
        CP_ASYNC16(s0 + off0,          Kh_g + kidx);
        CP_ASYNC16(s0 + off1,          Kh_g + kidx + 8);
        CP_ASYNC16(s0 + 8192 + off0,   Kl_g + kidx);
        CP_ASYNC16(s0 + 8192 + off1,   Kl_g + kidx + 8);
        CP_ASYNC16(s0 + 16384 + off0,  Vf_g + kidx);
        CP_ASYNC16(s0 + 16384 + off1,  Vf_g + kidx + 8);
        CP_COMMIT();
    }
    if (tid < 64)
        pads[kt_lo & 1][tid] = padb[kt_lo * 64 + tid] ? -1e30f : 0.f;

    float Oacc[4][4];
#pragma unroll
    for (int nt = 0; nt < 4; ++nt)
#pragma unroll
        for (int q = 0; q < 4; ++q) Oacc[nt][q] = 0.f;

    const int row0 = 16 * wq + r;
    float m0r = -1e30f, m1r = -1e30f, l0r = 0.f, l1r = 0.f;

    int st = 0;
    for (int kt = kt_lo; kt <= qt; ++kt) {
        CP_WAIT0();
        __syncthreads();   // B1

        if (kt < qt) {
            const size_t kidx =
                ((size_t)(b * SEQ_L + (kt + 1) * 64 + ldRow)) * D_MODEL + gcol;
            const uint32_t s1 = smb + AKV0 + (uint32_t)(st ^ 1) * AKV_STRIDE;
            CP_ASYNC16(s1 + off0,          Kh_g + kidx);
            CP_ASYNC16(s1 + off1,          Kh_g + kidx + 8);
            CP_ASYNC16(s1 + 8192 + off0,   Kl_g + kidx);
            CP_ASYNC16(s1 + 8192 + off1,   Kl_g + kidx + 8);
            CP_ASYNC16(s1 + 16384 + off0,  Vf_g + kidx);
            CP_ASYNC16(s1 + 16384 + off1,  Vf_g + kidx + 8);
            CP_COMMIT();
            if (tid < 64)
                pads[(kt + 1) & 1][tid] = padb[(kt + 1) * 64 + tid] ? -1e30f : 0.f;
        }

        const uint32_t stb  = smb + AKV0 + (uint32_t)st * AKV_STRIDE;
        const uint32_t kh_b = stb + khRel;
        const uint32_t kl_b = kh_b + 8192;
        const uint32_t vf_b = stb + vfRel;
        const float* padc = pads[kt & 1];

        // ---- S = Q.K^T (bf16x2 3-term) ----
        float Sacc[4][4];
#pragma unroll
        for (int nt = 0; nt < 4; ++nt)
#pragma unroll
            for (int q = 0; q < 4; ++q) Sacc[nt][q] = 0.f;

#pragma unroll
        for (int ks = 0; ks < 4; ++ks) {
            uint32_t ah[4], al[4];
            const uint32_t axo = ((uint32_t)((2 * ks + aCa) ^ aR7) << 4);
            ldsm_x4(qh_b + axo, ah);
            ldsm_x4(ql_b + axo, al);
            uint32_t bhf[2][4], blf[2][4];
            const uint32_t kxo = ((uint32_t)((2 * ks + kCa) ^ kR7) << 4);
#pragma unroll
            for (int p = 0; p < 2; ++p) {
                ldsm_x4(kh_b + (uint32_t)p * 2048 + kxo, bhf[p]);
                ldsm_x4(kl_b + (uint32_t)p * 2048 + kxo, blf[p]);
            }
#pragma unroll
            for (int nt = 0; nt < 4; ++nt) {
                const uint32_t bh0 = bhf[nt >> 1][(nt & 1) << 1];
                const uint32_t bh1 = bhf[nt >> 1][((nt & 1) << 1) + 1];
                const uint32_t bl0 = blf[nt >> 1][(nt & 1) << 1];
                const uint32_t bl1 = blf[nt >> 1][((nt & 1) << 1) + 1];
                mma_bf16(Sacc[nt], ah, bh0, bh1);
                mma_bf16(Sacc[nt], ah, bl0, bl1);
                mma_bf16(Sacc[nt], al, bh0, bh1);
            }
        }

        // ---- mask + ALiBi + row max ----
        const int gi0 = qt * 64 + row0;
        const int gi1 = gi0 + 8;
        float mx0 = -1e30f, mx1 = -1e30f;
#pragma unroll
        for (int nt = 0; nt < 4; ++nt) {
            const int jl = 32 * wk + 8 * nt + 2 * c;
            const int gj0 = kt * 64 + jl, gj1 = gj0 + 1;
            const float pd0 = padc[jl], pd1 = padc[jl + 1];
            float s;
            s = Sacc[nt][0] + slope * (float)(gj0 - gi0) + pd0;
            if (gj0 > gi0 || gj0 < gi0 - WINDOW) s = -1e30f;
            Sacc[nt][0] = s; mx0 = fmaxf(mx0, s);
            s = Sacc[nt][1] + slope * (float)(gj1 - gi0) + pd1;
            if (gj1 > gi0 || gj1 < gi0 - WINDOW) s = -1e30f;
            Sacc[nt][1] = s; mx0 = fmaxf(mx0, s);
            s = Sacc[nt][2] + slope * (float)(gj0 - gi1) + pd0;
            if (gj0 > gi1 || gj0 < gi1 - WINDOW) s = -1e30f;
            Sacc[nt][2] = s; mx1 = fmaxf(mx1, s);
            s = Sacc[nt][3] + slope * (float)(gj1 - gi1) + pd1;
            if (gj1 > gi1 || gj1 < gi1 - WINDOW) s = -1e30f;
            Sacc[nt][3] = s; mx1 = fmaxf(mx1, s);
        }
        mx0 = fmaxf(mx0, __shfl_xor_sync(0xffffffffu, mx0, 1));
        mx0 = fmaxf(mx0, __shfl_xor_sync(0xffffffffu, mx0, 2));
        mx1 = fmaxf(mx1, __shfl_xor_sync(0xffffffffu, mx1, 1));
        mx1 = fmaxf(mx1, __shfl_xor_sync(0xffffffffu, mx1, 2));
        if (c == 0) { redA[row0][wk] = mx0; redA[row0 + 8][wk] = mx1; }
        __syncthreads();   // B2

        const float mt0 = fmaxf(redA[row0][0], redA[row0][1]);
        const float mt1 = fmaxf(redA[row0 + 8][0], redA[row0 + 8][1]);
        const float mn0 = fmaxf(m0r, mt0);
        const float mn1 = fmaxf(m1r, mt1);
        const float sc0 = __expf(m0r - mn0);
        const float sc1 = __expf(m1r - mn1);
        m0r = mn0; m1r = mn1;
        l0r *= sc0; l1r *= sc1;

        // ---- P = exp(S-m) -> fp16 plane; rescale O ----
        float rs0 = 0.f, rs1 = 0.f;
        const uint32_t prow0 = (uint32_t)row0 * 128;
        const uint32_t prow1 = (uint32_t)(row0 + 8) * 128;
        const uint32_t pxr = (uint32_t)(row0 & 7);
#pragma unroll
        for (int nt = 0; nt < 4; ++nt) {
            float p0 = __expf(Sacc[nt][0] - mn0);
            float p1 = __expf(Sacc[nt][1] - mn0);
            float p2 = __expf(Sacc[nt][2] - mn1);
            float p3 = __expf(Sacc[nt][3] - mn1);
            rs0 += p0 + p1; rs1 += p2 + p3;
            const uint32_t cxo = (((uint32_t)(4 * wk + nt) ^ pxr) << 4) + 4 * c;
            __half2 ph0 = __floats2half2_rn(p0, p1);
            __half2 ph1 = __floats2half2_rn(p2, p3);
            *(__half2*)(smc + AP_F + prow0 + cxo) = ph0;
            *(__half2*)(smc + AP_F + prow1 + cxo) = ph1;
            Oacc[nt][0] *= sc0; Oacc[nt][1] *= sc0;
            Oacc[nt][2] *= sc1; Oacc[nt][3] *= sc1;
        }
        rs0 += __shfl_xor_sync(0xffffffffu, rs0, 1);
        rs0 += __shfl_xor_sync(0xffffffffu, rs0, 2);
        rs1 += __shfl_xor_sync(0xffffffffu, rs1, 1);
        rs1 += __shfl_xor_sync(0xffffffffu, rs1, 2);
        if (c == 0) { redB[row0][wk] = rs0; redB[row0 + 8][wk] = rs1; }
        __syncthreads();   // B3

        l0r += redB[row0][0] + redB[row0][1];
        l1r += redB[row0 + 8][0] + redB[row0 + 8][1];

        // ---- O += P.V (fp16 single-plane) ----
#pragma unroll
        for (int ks = 0; ks < 4; ++ks) {
            uint32_t af[4];
            const uint32_t axo = ((uint32_t)((2 * ks + aCa) ^ aR7) << 4);
            ldsm_x4(pf_b + axo, af);
#pragma unroll
            for (int p = 0; p < 2; ++p) {
                uint32_t bv[4];
                const uint32_t vxo = (uint32_t)ks * 2048 +
                    (((uint32_t)(vCa + 2 * p) ^ vR7) << 4);
                ldsm_x4_t(vf_b + vxo, bv);
#pragma unroll
                for (int q2 = 0; q2 < 2; ++q2)
                    mma_fp16(Oacc[2 * p + q2], af, bv[2 * q2], bv[2 * q2 + 1]);
            }
        }
        st ^= 1;
    }

    const float inv0 = 1.f / l0r;
    const float inv1 = 1.f / l1r;
    const int gi0 = qt * 64 + row0;
    __half* Ob = O + ((size_t)b * SEQ_L + gi0) * D_MODEL + h * HEAD_DIM;
#pragma unroll
    for (int nt = 0; nt < 4; ++nt) {
        const int dcol = 32 * wk + 8 * nt + 2 * c;
        __half2 o0 = __floats2half2_rn(Oacc[nt][0] * inv0, Oacc[nt][1] * inv0);
        __half2 o1 = __floats2half2_rn(Oacc[nt][2] * inv1, Oacc[nt][3] * inv1);
        *(__half2*)(Ob + dcol)               = o0;
        *(__half2*)(Ob + 8 * D_MODEL + dcol) = o1;
    }
}

// ---------------------------------------------------------------------------
extern "C" void kernel_launch(void* const* d_in, const int* in_sizes, int n_in,
                              void* d_out, int out_size)
{
    const float* x  = (const float*)d_in[0];
    const unsigned char* pad = (const unsigned char*)d_in[1];
    const float* Wq = (const float*)d_in[2];
    const float* bq = (const float*)d_in[3];
    const float* Wk = (const float*)d_in[4];
    const float* bk = (const float*)d_in[5];
    const float* Wv = (const float*)d_in[6];
    const float* bv = (const float*)d_in[7];
    const float* Wo = (const float*)d_in[8];
    const float* bo = (const float*)d_in[9];
    float* out = (float*)d_out;

    __nv_bfloat16 *qh, *ql, *kh, *kl;
    __half *vf, *att, *xh, *wh;
    cudaGetSymbolAddress((void**)&qh,  g_qh);
    cudaGetSymbolAddress((void**)&ql,  g_ql);
    cudaGetSymbolAddress((void**)&kh,  g_kh);
    cudaGetSymbolAddress((void**)&kl,  g_kl);
    cudaGetSymbolAddress((void**)&vf,  g_vf);
    cudaGetSymbolAddress((void**)&att, g_att);
    cudaGetSymbolAddress((void**)&xh,  g_xh);
    cudaGetSymbolAddress((void**)&wh,  g_wh);

    cudaFuncSetAttribute(gemm_fp16_cp3<true>,
                         cudaFuncAttributeMaxDynamicSharedMemorySize,
                         G2_SMEM_BYTES);
    cudaFuncSetAttribute(gemm_fp16_cp3<false>,
                         cudaFuncAttributeMaxDynamicSharedMemorySize,
                         G2_SMEM_BYTES);
    cudaFuncSetAttribute(attn_alibi_cp,
                         cudaFuncAttributeMaxDynamicSharedMemorySize,
                         ATTN_SMEM_BYTES);

    const int WN  = D_MODEL * D_MODEL;
    const int xn4 = MTOT * D_MODEL / 4;
    const int wn4 = WN / 4;
    dim3 rgrid((xn4 + 255) / 256, 5);
    round_fp16_multi<<<rgrid, 256>>>((const float4*)x, xh,
                                     (const float4*)Wq, (const float4*)Wk,
                                     (const float4*)Wv, (const float4*)Wo,
                                     wh, xn4, wn4);

    dim3 qkv_grid(D_MODEL / 128, MTOT / 128, 3);
    gemm_fp16_cp3<true><<<qkv_grid, 256, G2_SMEM_BYTES>>>(
        xh, wh, (size_t)WN, bq, bk, bv, nullptr,
        qh, ql, kh, kl, vf, MTOT, D_MODEL, D_MODEL);

    dim3 agrid(SEQ_L / 64, BATCH * N_HEADS);   // (32, 64)
    attn_alibi_cp<<<agrid, 256, ATTN_SMEM_BYTES>>>(
        qh, ql, kh, kl, vf, pad, att);

    dim3 o_grid(D_MODEL / 128, MTOT / 128, 1);
    gemm_fp16_cp3<false><<<o_grid, 256, G2_SMEM_BYTES>>>(
        att, wh + 3 * (size_t)WN, (size_t)0, bo, bo, bo, out,
        nullptr, nullptr, nullptr, nullptr, nullptr,
        MTOT, D_MODEL, D_MODEL);
}